// round 1
// baseline (speedup 1.0000x reference)
#include <cuda_runtime.h>
#include <cuda_bf16.h>
#include <math.h>

#define N_NODES 2048
#define DMODEL  256
#define NHEAD   8
#define DK      32
#define NEDGE   65536
#define HID     512

// ---------------- scratch (static device memory; no allocations) ----------------
__device__ float g_Q[N_NODES * DMODEL];
__device__ float g_K[N_NODES * DMODEL];
__device__ float g_V[N_NODES * DMODEL];
__device__ float g_eb[NEDGE * NHEAD];
__device__ int   g_win[N_NODES * N_NODES];
__device__ float g_attn[N_NODES * DMODEL];
__device__ float g_Y[N_NODES * DMODEL];
__device__ float g_h1[N_NODES * DMODEL];
__device__ float g_x2[N_NODES * DMODEL];
__device__ float g_G[N_NODES * HID];

// ---------------- reset winner map ----------------
__global__ __launch_bounds__(1024) void reset_winner_kernel() {
    int i = blockIdx.x * blockDim.x + threadIdx.x;   // 1M threads, int4 each
    ((int4*)g_win)[i] = make_int4(-1, -1, -1, -1);
}

// ---------------- edge bias + scatter winner ----------------
__global__ __launch_bounds__(256) void edge_kernel(const float* __restrict__ ea,
                                                   const float* __restrict__ We,
                                                   const float* __restrict__ be,
                                                   const int*   __restrict__ eidx) {
    int e = blockIdx.x * blockDim.x + threadIdx.x;
    float a[7];
#pragma unroll
    for (int j = 0; j < 7; j++) a[j] = ea[e * 7 + j];
#pragma unroll
    for (int hh = 0; hh < 8; hh++) {
        float v = be[hh];
#pragma unroll
        for (int j = 0; j < 7; j++) v += a[j] * We[j * 8 + hh];
        g_eb[e * 8 + hh] = v;
    }
    int src = eidx[e];
    int dst = eidx[NEDGE + e];
    atomicMax(&g_win[src * N_NODES + dst], e);
}

// ---------------- generic SGEMM: C = A(MxK) @ B(KxN) + bias [, gelu] [, +R] ----------
// BM=BN=64, BK=16, 256 threads, 4x4 register tiles.
__global__ __launch_bounds__(256) void gemm64(const float* __restrict__ A,
                                              const float* __restrict__ B,
                                              const float* __restrict__ bias,
                                              const float* __restrict__ R,
                                              float* __restrict__ C,
                                              int M, int N, int K, int gelu) {
    __shared__ float As[16][68];   // transposed: As[kk][m]
    __shared__ float Bs[16][68];
    const int tid = threadIdx.x;
    const int tn = tid & 15, tm = tid >> 4;
    const int bm = blockIdx.y * 64, bn = blockIdx.x * 64;
    const int arow = tid >> 2, acol = (tid & 3) << 2;
    const int brow = tid >> 4, bcol = (tid & 15) << 2;
    const float* Aptr = A + (bm + arow) * K + acol;
    const float* Bptr = B + brow * N + bn + bcol;
    float acc[4][4] = {};

    for (int k0 = 0; k0 < K; k0 += 16) {
        float4 a4 = *(const float4*)(Aptr + k0);
        float4 b4 = *(const float4*)(Bptr + (size_t)k0 * N);
        __syncthreads();
        As[acol + 0][arow] = a4.x;
        As[acol + 1][arow] = a4.y;
        As[acol + 2][arow] = a4.z;
        As[acol + 3][arow] = a4.w;
        *(float4*)&Bs[brow][bcol] = b4;
        __syncthreads();
#pragma unroll
        for (int kk = 0; kk < 16; kk++) {
            float4 av = *(const float4*)&As[kk][tm << 2];
            float4 bv = *(const float4*)&Bs[kk][tn << 2];
            float a[4] = {av.x, av.y, av.z, av.w};
            float b[4] = {bv.x, bv.y, bv.z, bv.w};
#pragma unroll
            for (int i = 0; i < 4; i++)
#pragma unroll
                for (int j = 0; j < 4; j++) acc[i][j] += a[i] * b[j];
        }
    }

    const int crow = bm + (tm << 2), ccol = bn + (tn << 2);
#pragma unroll
    for (int i = 0; i < 4; i++) {
        float o[4];
#pragma unroll
        for (int j = 0; j < 4; j++) {
            float v = acc[i][j] + bias[ccol + j];
            if (gelu) v = v * normcdff(v);           // exact gelu: x * Phi(x)
            if (R) v += R[(size_t)(crow + i) * N + ccol + j];
            o[j] = v;
        }
        float4 o4 = make_float4(o[0], o[1], o[2], o[3]);
        *(float4*)&C[(size_t)(crow + i) * N + ccol] = o4;
    }
}

// ---------------- flash attention per (query-tile=32, head) ----------------
// block 256: thread = (qi = tid>>3, g = tid&7); each thread: 1 query x 4 keys/tile (float4).
__global__ __launch_bounds__(256) void attn_kernel(const float* __restrict__ Q,
                                                   const float* __restrict__ K,
                                                   const float* __restrict__ V,
                                                   float* __restrict__ Out) {
    __shared__ float Ks[32][36];   // transposed [d][k]
    __shared__ float Vs[32][36];   // transposed [d][k]
    __shared__ float Qs[32][36];   // [q][d]
    __shared__ int   Ws[32][36];   // [q][k]

    const int h  = blockIdx.y;
    const int qb = blockIdx.x * 32;
    const int tid = threadIdx.x;
    const int qi = tid >> 3, g = tid & 7;
    const int ldrow = tid >> 3;           // 0..31
    const int ldc4  = (tid & 7) << 2;     // 0,4,..,28

    // stage Q tile
    {
        float4 t = *(const float4*)&Q[(size_t)(qb + ldrow) * DMODEL + h * DK + ldc4];
        *(float4*)&Qs[ldrow][ldc4] = t;
    }
    __syncthreads();
    float qreg[32];
#pragma unroll
    for (int j = 0; j < 8; j++) {
        float4 t = *(const float4*)&Qs[qi][j << 2];
        qreg[4 * j + 0] = t.x; qreg[4 * j + 1] = t.y;
        qreg[4 * j + 2] = t.z; qreg[4 * j + 3] = t.w;
    }

    float m = -1e30f, l = 0.f;
    float O[32];
#pragma unroll
    for (int d = 0; d < 32; d++) O[d] = 0.f;

    const float SCALE = 0.17677669529663688f;  // 1/sqrt(32)

    for (int kt = 0; kt < N_NODES / 32; kt++) {
        const int kb = kt << 5;
        __syncthreads();
        {
            float4 k4 = *(const float4*)&K[(size_t)(kb + ldrow) * DMODEL + h * DK + ldc4];
            float4 v4 = *(const float4*)&V[(size_t)(kb + ldrow) * DMODEL + h * DK + ldc4];
            Ks[ldc4 + 0][ldrow] = k4.x; Ks[ldc4 + 1][ldrow] = k4.y;
            Ks[ldc4 + 2][ldrow] = k4.z; Ks[ldc4 + 3][ldrow] = k4.w;
            Vs[ldc4 + 0][ldrow] = v4.x; Vs[ldc4 + 1][ldrow] = v4.y;
            Vs[ldc4 + 2][ldrow] = v4.z; Vs[ldc4 + 3][ldrow] = v4.w;
            int4 w4 = *(const int4*)&g_win[(size_t)(qb + ldrow) * N_NODES + kb + ldc4];
            *(int4*)&Ws[ldrow][ldc4] = w4;
        }
        __syncthreads();

        // scores for 4 keys
        float s0 = 0.f, s1 = 0.f, s2 = 0.f, s3 = 0.f;
#pragma unroll
        for (int d = 0; d < 32; d++) {
            float4 k4 = *(const float4*)&Ks[d][g << 2];
            float qd = qreg[d];
            s0 += qd * k4.x; s1 += qd * k4.y; s2 += qd * k4.z; s3 += qd * k4.w;
        }
        s0 *= SCALE; s1 *= SCALE; s2 *= SCALE; s3 *= SCALE;
        {
            int w;
            w = Ws[qi][(g << 2) + 0]; if (w >= 0) s0 += g_eb[w * 8 + h];
            w = Ws[qi][(g << 2) + 1]; if (w >= 0) s1 += g_eb[w * 8 + h];
            w = Ws[qi][(g << 2) + 2]; if (w >= 0) s2 += g_eb[w * 8 + h];
            w = Ws[qi][(g << 2) + 3]; if (w >= 0) s3 += g_eb[w * 8 + h];
        }

        // online softmax (group of 8 lanes shares query qi)
        float tmax = fmaxf(fmaxf(s0, s1), fmaxf(s2, s3));
        tmax = fmaxf(tmax, __shfl_xor_sync(0xffffffffu, tmax, 1));
        tmax = fmaxf(tmax, __shfl_xor_sync(0xffffffffu, tmax, 2));
        tmax = fmaxf(tmax, __shfl_xor_sync(0xffffffffu, tmax, 4));
        float mnew = fmaxf(m, tmax);
        float corr = __expf(m - mnew);
        m = mnew;
        l *= corr;
#pragma unroll
        for (int d = 0; d < 32; d++) O[d] *= corr;

        float p0 = __expf(s0 - mnew);
        float p1 = __expf(s1 - mnew);
        float p2 = __expf(s2 - mnew);
        float p3 = __expf(s3 - mnew);
        l += p0 + p1 + p2 + p3;

#pragma unroll
        for (int d = 0; d < 32; d++) {
            float4 v4 = *(const float4*)&Vs[d][g << 2];
            O[d] += p0 * v4.x + p1 * v4.y + p2 * v4.z + p3 * v4.w;
        }
    }

    // reduce l across the 8-lane group
    l += __shfl_xor_sync(0xffffffffu, l, 1);
    l += __shfl_xor_sync(0xffffffffu, l, 2);
    l += __shfl_xor_sync(0xffffffffu, l, 4);

    // reduce-scatter O across group: lane g ends with dims 4g..4g+3 in O[0..3]
#pragma unroll
    for (int i = 0; i < 16; i++) {
        float a = O[i], b = O[16 + i];
        float ra = __shfl_xor_sync(0xffffffffu, a, 4);
        float rb = __shfl_xor_sync(0xffffffffu, b, 4);
        O[i] = (g & 4) ? (b + rb) : (a + ra);
    }
#pragma unroll
    for (int i = 0; i < 8; i++) {
        float a = O[i], b = O[8 + i];
        float ra = __shfl_xor_sync(0xffffffffu, a, 2);
        float rb = __shfl_xor_sync(0xffffffffu, b, 2);
        O[i] = (g & 2) ? (b + rb) : (a + ra);
    }
#pragma unroll
    for (int i = 0; i < 4; i++) {
        float a = O[i], b = O[4 + i];
        float ra = __shfl_xor_sync(0xffffffffu, a, 1);
        float rb = __shfl_xor_sync(0xffffffffu, b, 1);
        O[i] = (g & 1) ? (b + rb) : (a + ra);
    }

    float inv = 1.f / l;
    float4 res = make_float4(O[0] * inv, O[1] * inv, O[2] * inv, O[3] * inv);
    *(float4*)&Out[(size_t)(qb + qi) * DMODEL + h * DK + (g << 2)] = res;
}

// ---------------- fused double LayerNorm: Y -> h1 (ln1), h1 -> x2 (fln) ----------------
__global__ __launch_bounds__(256) void ln_kernel(const float* __restrict__ Y,
                                                 const float* __restrict__ g1,
                                                 const float* __restrict__ b1,
                                                 const float* __restrict__ g2,
                                                 const float* __restrict__ b2,
                                                 float* __restrict__ H1,
                                                 float* __restrict__ X2) {
    const int lane = threadIdx.x & 31;
    const int row  = blockIdx.x * 8 + (threadIdx.x >> 5);
    const float* y = Y + (size_t)row * DMODEL;
    float v[8];
#pragma unroll
    for (int j = 0; j < 8; j++) v[j] = y[lane + 32 * j];

    float s = 0.f;
#pragma unroll
    for (int j = 0; j < 8; j++) s += v[j];
#pragma unroll
    for (int o = 16; o; o >>= 1) s += __shfl_xor_sync(0xffffffffu, s, o);
    float mu = s * (1.f / 256.f);
    float q = 0.f;
#pragma unroll
    for (int j = 0; j < 8; j++) { float d = v[j] - mu; q += d * d; }
#pragma unroll
    for (int o = 16; o; o >>= 1) q += __shfl_xor_sync(0xffffffffu, q, o);
    float rs = rsqrtf(q * (1.f / 256.f) + 1e-5f);

    float hv[8];
#pragma unroll
    for (int j = 0; j < 8; j++) {
        int c = lane + 32 * j;
        hv[j] = (v[j] - mu) * rs * g1[c] + b1[c];
        H1[(size_t)row * DMODEL + c] = hv[j];
    }

    s = 0.f;
#pragma unroll
    for (int j = 0; j < 8; j++) s += hv[j];
#pragma unroll
    for (int o = 16; o; o >>= 1) s += __shfl_xor_sync(0xffffffffu, s, o);
    mu = s * (1.f / 256.f);
    q = 0.f;
#pragma unroll
    for (int j = 0; j < 8; j++) { float d = hv[j] - mu; q += d * d; }
#pragma unroll
    for (int o = 16; o; o >>= 1) q += __shfl_xor_sync(0xffffffffu, q, o);
    rs = rsqrtf(q * (1.f / 256.f) + 1e-5f);
#pragma unroll
    for (int j = 0; j < 8; j++) {
        int c = lane + 32 * j;
        X2[(size_t)row * DMODEL + c] = (hv[j] - mu) * rs * g2[c] + b2[c];
    }
}

// ---------------- launch ----------------
extern "C" void kernel_launch(void* const* d_in, const int* in_sizes, int n_in,
                              void* d_out, int out_size) {
    const float* h    = (const float*)d_in[0];
    const float* ea   = (const float*)d_in[1];
    const float* Wq   = (const float*)d_in[2];
    const float* bq   = (const float*)d_in[3];
    const float* Wk   = (const float*)d_in[4];
    const float* bk   = (const float*)d_in[5];
    const float* Wv   = (const float*)d_in[6];
    const float* bv   = (const float*)d_in[7];
    const float* Wo   = (const float*)d_in[8];
    const float* bo   = (const float*)d_in[9];
    const float* We   = (const float*)d_in[10];
    const float* be   = (const float*)d_in[11];
    const float* ln1g = (const float*)d_in[12];
    const float* ln1b = (const float*)d_in[13];
    const float* flng = (const float*)d_in[14];
    const float* flnb = (const float*)d_in[15];
    const float* W1   = (const float*)d_in[16];
    const float* b1   = (const float*)d_in[17];
    const float* W2   = (const float*)d_in[18];
    const float* b2   = (const float*)d_in[19];
    const int*   eidx = (const int*)d_in[20];
    float* out = (float*)d_out;

    float *pQ, *pK, *pV, *pAttn, *pY, *pH1, *pX2, *pG;
    cudaGetSymbolAddress((void**)&pQ,    g_Q);
    cudaGetSymbolAddress((void**)&pK,    g_K);
    cudaGetSymbolAddress((void**)&pV,    g_V);
    cudaGetSymbolAddress((void**)&pAttn, g_attn);
    cudaGetSymbolAddress((void**)&pY,    g_Y);
    cudaGetSymbolAddress((void**)&pH1,   g_h1);
    cudaGetSymbolAddress((void**)&pX2,   g_x2);
    cudaGetSymbolAddress((void**)&pG,    g_G);

    reset_winner_kernel<<<1024, 1024>>>();
    edge_kernel<<<NEDGE / 256, 256>>>(ea, We, be, eidx);

    dim3 gQKV(DMODEL / 64, N_NODES / 64);
    gemm64<<<gQKV, 256>>>(h, Wq, bq, nullptr, pQ, N_NODES, DMODEL, DMODEL, 0);
    gemm64<<<gQKV, 256>>>(h, Wk, bk, nullptr, pK, N_NODES, DMODEL, DMODEL, 0);
    gemm64<<<gQKV, 256>>>(h, Wv, bv, nullptr, pV, N_NODES, DMODEL, DMODEL, 0);

    attn_kernel<<<dim3(N_NODES / 32, NHEAD), 256>>>(pQ, pK, pV, pAttn);

    gemm64<<<gQKV, 256>>>(pAttn, Wo, bo, h, pY, N_NODES, DMODEL, DMODEL, 0);

    ln_kernel<<<N_NODES / 8, 256>>>(pY, ln1g, ln1b, flng, flnb, pH1, pX2);

    gemm64<<<dim3(HID / 64, N_NODES / 64), 256>>>(pX2, W1, b1, nullptr, pG,
                                                  N_NODES, HID, DMODEL, 1);
    gemm64<<<dim3(DMODEL / 64, N_NODES / 64), 256>>>(pG, W2, b2, pH1, out,
                                                     N_NODES, DMODEL, HID, 0);
}

// round 2
// speedup vs baseline: 1.0687x; 1.0687x over previous
#include <cuda_runtime.h>
#include <cuda_bf16.h>
#include <math.h>

#define N_NODES 2048
#define DMODEL  256
#define NHEAD   8
#define DK      32
#define NEDGE   65536
#define HID     512

typedef unsigned long long ull;

// ---- packed f32x2 helpers (sm_103a) ----
__device__ __forceinline__ ull fma2(ull a, ull b, ull c) {
    ull d; asm("fma.rn.f32x2 %0,%1,%2,%3;" : "=l"(d) : "l"(a), "l"(b), "l"(c)); return d;
}
__device__ __forceinline__ ull add2(ull a, ull b) {
    ull d; asm("add.rn.f32x2 %0,%1,%2;" : "=l"(d) : "l"(a), "l"(b)); return d;
}
__device__ __forceinline__ ull pack2(float x, float y) {
    ull r; asm("mov.b64 %0,{%1,%2};" : "=l"(r) : "f"(x), "f"(y)); return r;
}
__device__ __forceinline__ float2 unpack2(ull v) {
    float x, y; asm("mov.b64 {%0,%1},%2;" : "=f"(x), "=f"(y) : "l"(v));
    return make_float2(x, y);
}

// ---------------- scratch ----------------
__device__ float g_Q[N_NODES * DMODEL];
__device__ float g_K[N_NODES * DMODEL];
__device__ float g_V[N_NODES * DMODEL];
__device__ float g_eb[NEDGE * NHEAD];
__device__ int   g_win[N_NODES * N_NODES];
__device__ float g_attn[N_NODES * DMODEL];
__device__ float g_Y[N_NODES * DMODEL];
__device__ float g_h1[N_NODES * DMODEL];
__device__ float g_x2[N_NODES * DMODEL];
__device__ float g_G[N_NODES * HID];

// ---------------- reset winner map ----------------
__global__ __launch_bounds__(1024) void reset_winner_kernel() {
    int i = blockIdx.x * blockDim.x + threadIdx.x;
    ((int4*)g_win)[i] = make_int4(-1, -1, -1, -1);
}

// ---------------- edge bias + scatter winner ----------------
__global__ __launch_bounds__(256) void edge_kernel(const float* __restrict__ ea,
                                                   const float* __restrict__ We,
                                                   const float* __restrict__ be,
                                                   const int*   __restrict__ eidx) {
    int e = blockIdx.x * blockDim.x + threadIdx.x;
    float a[7];
#pragma unroll
    for (int j = 0; j < 7; j++) a[j] = ea[e * 7 + j];
#pragma unroll
    for (int hh = 0; hh < 8; hh++) {
        float v = be[hh];
#pragma unroll
        for (int j = 0; j < 7; j++) v += a[j] * We[j * 8 + hh];
        g_eb[e * 8 + hh] = v;
    }
    int src = eidx[e];
    int dst = eidx[NEDGE + e];
    atomicMax(&g_win[src * N_NODES + dst], e);
}

// ---------------- SGEMM body: 64x64 tile, BK=16, 256 threads, f32x2 math ----------
__device__ __forceinline__ void gemm_body(const float* __restrict__ A,
                                          const float* __restrict__ B,
                                          const float* __restrict__ bias,
                                          const float* __restrict__ R,
                                          float* __restrict__ C,
                                          int N, int K, int gelu,
                                          int bm, int bn) {
    __shared__ float As[16][68];   // transposed: As[kk][m]
    __shared__ float Bs[16][68];
    const int tid = threadIdx.x;
    const int tn = tid & 15, tm = tid >> 4;
    const int arow = tid >> 2, acol = (tid & 3) << 2;
    const int brow = tid >> 4, bcol = (tid & 15) << 2;
    const float* Aptr = A + (size_t)(bm + arow) * K + acol;
    const float* Bptr = B + (size_t)brow * N + bn + bcol;
    ull acc[4][2];
#pragma unroll
    for (int i = 0; i < 4; i++) { acc[i][0] = 0ull; acc[i][1] = 0ull; }

    for (int k0 = 0; k0 < K; k0 += 16) {
        float4 a4 = *(const float4*)(Aptr + k0);
        float4 b4 = *(const float4*)(Bptr + (size_t)k0 * N);
        __syncthreads();
        As[acol + 0][arow] = a4.x;
        As[acol + 1][arow] = a4.y;
        As[acol + 2][arow] = a4.z;
        As[acol + 3][arow] = a4.w;
        *(float4*)&Bs[brow][bcol] = b4;
        __syncthreads();
#pragma unroll
        for (int kk = 0; kk < 16; kk++) {
            float4 av = *(const float4*)&As[kk][tm << 2];
            ulonglong2 bv = *(const ulonglong2*)&Bs[kk][tn << 2];
            ull a0 = pack2(av.x, av.x);
            ull a1 = pack2(av.y, av.y);
            ull a2 = pack2(av.z, av.z);
            ull a3 = pack2(av.w, av.w);
            acc[0][0] = fma2(a0, bv.x, acc[0][0]); acc[0][1] = fma2(a0, bv.y, acc[0][1]);
            acc[1][0] = fma2(a1, bv.x, acc[1][0]); acc[1][1] = fma2(a1, bv.y, acc[1][1]);
            acc[2][0] = fma2(a2, bv.x, acc[2][0]); acc[2][1] = fma2(a2, bv.y, acc[2][1]);
            acc[3][0] = fma2(a3, bv.x, acc[3][0]); acc[3][1] = fma2(a3, bv.y, acc[3][1]);
        }
    }

    const int crow = bm + (tm << 2), ccol = bn + (tn << 2);
#pragma unroll
    for (int i = 0; i < 4; i++) {
        float2 u0 = unpack2(acc[i][0]);
        float2 u1 = unpack2(acc[i][1]);
        float o[4] = {u0.x, u0.y, u1.x, u1.y};
#pragma unroll
        for (int j = 0; j < 4; j++) {
            float v = o[j] + bias[ccol + j];
            if (gelu) v = v * normcdff(v);
            if (R) v += R[(size_t)(crow + i) * N + ccol + j];
            o[j] = v;
        }
        *(float4*)&C[(size_t)(crow + i) * N + ccol] =
            make_float4(o[0], o[1], o[2], o[3]);
    }
}

__global__ __launch_bounds__(256) void gemm64(const float* __restrict__ A,
                                              const float* __restrict__ B,
                                              const float* __restrict__ bias,
                                              const float* __restrict__ R,
                                              float* __restrict__ C,
                                              int N, int K, int gelu) {
    gemm_body(A, B, bias, R, C, N, K, gelu, blockIdx.y * 64, blockIdx.x * 64);
}

// fused QKV: grid.x = 12 (3 matrices x 4 column tiles), grid.y = 32 row tiles
__global__ __launch_bounds__(256) void gemm_qkv(const float* __restrict__ A,
                                                const float* __restrict__ Wq,
                                                const float* __restrict__ bq,
                                                const float* __restrict__ Wk,
                                                const float* __restrict__ bk,
                                                const float* __restrict__ Wv,
                                                const float* __restrict__ bv) {
    int sel = blockIdx.x >> 2;
    int bn  = (blockIdx.x & 3) * 64;
    const float* B    = (sel == 0) ? Wq : (sel == 1) ? Wk : Wv;
    const float* bias = (sel == 0) ? bq : (sel == 1) ? bk : bv;
    float* C = (sel == 0) ? g_Q : (sel == 1) ? g_K : g_V;
    gemm_body(A, B, bias, nullptr, C, DMODEL, DMODEL, 0, blockIdx.y * 64, bn);
}

// ---------------- flash attention (no online max; scores bounded ~O(1)) ----------
// block 256: thread = (qi = tid>>3, g = tid&7); 1 query x 4 keys per thread per tile.
__global__ __launch_bounds__(256, 2) void attn_kernel(const float* __restrict__ Q,
                                                      const float* __restrict__ K,
                                                      const float* __restrict__ V,
                                                      float* __restrict__ Out) {
    __shared__ float Ks[32][36];    // [d][k] transposed
    __shared__ float Vs[32 * 32];   // [k][d] with XOR chunk swizzle
    __shared__ float Qs[32][36];
    __shared__ int   Ws[32][36];

    const int h  = blockIdx.y;
    const int qb = blockIdx.x * 32;
    const int tid = threadIdx.x;
    const int qi = tid >> 3, g = tid & 7;
    const int ldrow = tid >> 3;
    const int cc = tid & 7;
    const int ldc4 = cc << 2;
    const int vswz = ((cc ^ (ldrow & 7) ^ (ldrow >> 3)) << 2);

    // stage Q tile, pre-scale by 1/sqrt(dk)
    *(float4*)&Qs[ldrow][ldc4] =
        *(const float4*)&Q[(size_t)(qb + ldrow) * DMODEL + h * DK + ldc4];
    __syncthreads();
    const float SCALE = 0.17677669529663688f;
    float qs[32];
#pragma unroll
    for (int j = 0; j < 8; j++) {
        float4 t = *(const float4*)&Qs[qi][j << 2];
        qs[4 * j + 0] = t.x * SCALE; qs[4 * j + 1] = t.y * SCALE;
        qs[4 * j + 2] = t.z * SCALE; qs[4 * j + 3] = t.w * SCALE;
    }

    ull O2[16];
#pragma unroll
    for (int i = 0; i < 16; i++) O2[i] = 0ull;
    float l = 0.f;

    for (int kt = 0; kt < N_NODES / 32; kt++) {
        const int kb = kt << 5;
        __syncthreads();
        {
            float4 k4 = *(const float4*)&K[(size_t)(kb + ldrow) * DMODEL + h * DK + ldc4];
            float4 v4 = *(const float4*)&V[(size_t)(kb + ldrow) * DMODEL + h * DK + ldc4];
            int4  w4 = *(const int4*)&g_win[(size_t)(qb + ldrow) * N_NODES + kb + ldc4];
            Ks[ldc4 + 0][ldrow] = k4.x; Ks[ldc4 + 1][ldrow] = k4.y;
            Ks[ldc4 + 2][ldrow] = k4.z; Ks[ldc4 + 3][ldrow] = k4.w;
            *(float4*)&Vs[ldrow * 32 + vswz] = v4;
            *(int4*)&Ws[ldrow][ldc4] = w4;
        }
        __syncthreads();

        // scores: packed over key pairs
        ull s01 = 0ull, s23 = 0ull;
#pragma unroll
        for (int d = 0; d < 32; d++) {
            ulonglong2 kk2 = *(const ulonglong2*)&Ks[d][g << 2];
            ull qq = pack2(qs[d], qs[d]);
            s01 = fma2(qq, kk2.x, s01);
            s23 = fma2(qq, kk2.y, s23);
        }
        float2 sa = unpack2(s01), sb = unpack2(s23);
        float s0 = sa.x, s1 = sa.y, s2 = sb.x, s3 = sb.y;
        {
            int w;
            w = Ws[qi][(g << 2) + 0]; if (w >= 0) s0 += g_eb[w * 8 + h];
            w = Ws[qi][(g << 2) + 1]; if (w >= 0) s1 += g_eb[w * 8 + h];
            w = Ws[qi][(g << 2) + 2]; if (w >= 0) s2 += g_eb[w * 8 + h];
            w = Ws[qi][(g << 2) + 3]; if (w >= 0) s3 += g_eb[w * 8 + h];
        }
        float pv[4];
        pv[0] = __expf(s0); pv[1] = __expf(s1);
        pv[2] = __expf(s2); pv[3] = __expf(s3);
        l += (pv[0] + pv[1]) + (pv[2] + pv[3]);

        // PV: packed over d pairs, swizzled V rows (conflict-free across key lanes)
#pragma unroll
        for (int j = 0; j < 4; j++) {
            const int k = (g << 2) + j;
            const int sw = (k & 7) ^ (k >> 3);
            const float* vbase = &Vs[k * 32];
            ull pj = pack2(pv[j], pv[j]);
#pragma unroll
            for (int lc = 0; lc < 8; lc++) {
                ulonglong2 v = *(const ulonglong2*)&vbase[(lc ^ sw) << 2];
                O2[2 * lc + 0] = fma2(pj, v.x, O2[2 * lc + 0]);
                O2[2 * lc + 1] = fma2(pj, v.y, O2[2 * lc + 1]);
            }
        }
    }

    // reduce l over the 8-lane key group
    l += __shfl_xor_sync(0xffffffffu, l, 1);
    l += __shfl_xor_sync(0xffffffffu, l, 2);
    l += __shfl_xor_sync(0xffffffffu, l, 4);

    // reduce-scatter O2 (16 packed = 32 floats) -> lane g keeps floats 4g..4g+3
#pragma unroll
    for (int i = 0; i < 8; i++) {
        ull a = O2[i], b = O2[8 + i];
        ull ra = __shfl_xor_sync(0xffffffffu, a, 4);
        ull rb = __shfl_xor_sync(0xffffffffu, b, 4);
        O2[i] = (g & 4) ? add2(b, rb) : add2(a, ra);
    }
#pragma unroll
    for (int i = 0; i < 4; i++) {
        ull a = O2[i], b = O2[4 + i];
        ull ra = __shfl_xor_sync(0xffffffffu, a, 2);
        ull rb = __shfl_xor_sync(0xffffffffu, b, 2);
        O2[i] = (g & 2) ? add2(b, rb) : add2(a, ra);
    }
#pragma unroll
    for (int i = 0; i < 2; i++) {
        ull a = O2[i], b = O2[2 + i];
        ull ra = __shfl_xor_sync(0xffffffffu, a, 1);
        ull rb = __shfl_xor_sync(0xffffffffu, b, 1);
        O2[i] = (g & 1) ? add2(b, rb) : add2(a, ra);
    }

    float inv = 1.f / l;
    float2 r0 = unpack2(O2[0]);
    float2 r1 = unpack2(O2[1]);
    *(float4*)&Out[(size_t)(qb + qi) * DMODEL + h * DK + (g << 2)] =
        make_float4(r0.x * inv, r0.y * inv, r1.x * inv, r1.y * inv);
}

// ---------------- fused double LayerNorm ----------------
__global__ __launch_bounds__(256) void ln_kernel(const float* __restrict__ Y,
                                                 const float* __restrict__ g1,
                                                 const float* __restrict__ b1,
                                                 const float* __restrict__ g2,
                                                 const float* __restrict__ b2,
                                                 float* __restrict__ H1,
                                                 float* __restrict__ X2) {
    const int lane = threadIdx.x & 31;
    const int row  = blockIdx.x * 8 + (threadIdx.x >> 5);
    const float* y = Y + (size_t)row * DMODEL;
    float v[8];
#pragma unroll
    for (int j = 0; j < 8; j++) v[j] = y[lane + 32 * j];

    float s = 0.f;
#pragma unroll
    for (int j = 0; j < 8; j++) s += v[j];
#pragma unroll
    for (int o = 16; o; o >>= 1) s += __shfl_xor_sync(0xffffffffu, s, o);
    float mu = s * (1.f / 256.f);
    float q = 0.f;
#pragma unroll
    for (int j = 0; j < 8; j++) { float d = v[j] - mu; q += d * d; }
#pragma unroll
    for (int o = 16; o; o >>= 1) q += __shfl_xor_sync(0xffffffffu, q, o);
    float rs = rsqrtf(q * (1.f / 256.f) + 1e-5f);

    float hv[8];
#pragma unroll
    for (int j = 0; j < 8; j++) {
        int c = lane + 32 * j;
        hv[j] = (v[j] - mu) * rs * g1[c] + b1[c];
        H1[(size_t)row * DMODEL + c] = hv[j];
    }

    s = 0.f;
#pragma unroll
    for (int j = 0; j < 8; j++) s += hv[j];
#pragma unroll
    for (int o = 16; o; o >>= 1) s += __shfl_xor_sync(0xffffffffu, s, o);
    mu = s * (1.f / 256.f);
    q = 0.f;
#pragma unroll
    for (int j = 0; j < 8; j++) { float d = hv[j] - mu; q += d * d; }
#pragma unroll
    for (int o = 16; o; o >>= 1) q += __shfl_xor_sync(0xffffffffu, q, o);
    rs = rsqrtf(q * (1.f / 256.f) + 1e-5f);
#pragma unroll
    for (int j = 0; j < 8; j++) {
        int c = lane + 32 * j;
        X2[(size_t)row * DMODEL + c] = (hv[j] - mu) * rs * g2[c] + b2[c];
    }
}

// ---------------- launch ----------------
extern "C" void kernel_launch(void* const* d_in, const int* in_sizes, int n_in,
                              void* d_out, int out_size) {
    const float* h    = (const float*)d_in[0];
    const float* ea   = (const float*)d_in[1];
    const float* Wq   = (const float*)d_in[2];
    const float* bq   = (const float*)d_in[3];
    const float* Wk   = (const float*)d_in[4];
    const float* bk   = (const float*)d_in[5];
    const float* Wv   = (const float*)d_in[6];
    const float* bv   = (const float*)d_in[7];
    const float* Wo   = (const float*)d_in[8];
    const float* bo   = (const float*)d_in[9];
    const float* We   = (const float*)d_in[10];
    const float* be   = (const float*)d_in[11];
    const float* ln1g = (const float*)d_in[12];
    const float* ln1b = (const float*)d_in[13];
    const float* flng = (const float*)d_in[14];
    const float* flnb = (const float*)d_in[15];
    const float* W1   = (const float*)d_in[16];
    const float* b1   = (const float*)d_in[17];
    const float* W2   = (const float*)d_in[18];
    const float* b2   = (const float*)d_in[19];
    const int*   eidx = (const int*)d_in[20];
    float* out = (float*)d_out;

    float *pQ, *pK, *pV, *pAttn, *pY, *pH1, *pX2, *pG;
    cudaGetSymbolAddress((void**)&pQ,    g_Q);
    cudaGetSymbolAddress((void**)&pK,    g_K);
    cudaGetSymbolAddress((void**)&pV,    g_V);
    cudaGetSymbolAddress((void**)&pAttn, g_attn);
    cudaGetSymbolAddress((void**)&pY,    g_Y);
    cudaGetSymbolAddress((void**)&pH1,   g_h1);
    cudaGetSymbolAddress((void**)&pX2,   g_x2);
    cudaGetSymbolAddress((void**)&pG,    g_G);

    reset_winner_kernel<<<1024, 1024>>>();
    edge_kernel<<<NEDGE / 256, 256>>>(ea, We, be, eidx);

    gemm_qkv<<<dim3(12, 32), 256>>>(h, Wq, bq, Wk, bk, Wv, bv);

    attn_kernel<<<dim3(N_NODES / 32, NHEAD), 256>>>(pQ, pK, pV, pAttn);

    gemm64<<<dim3(4, 32), 256>>>(pAttn, Wo, bo, h, pY, DMODEL, DMODEL, 0);

    ln_kernel<<<N_NODES / 8, 256>>>(pY, ln1g, ln1b, flng, flnb, pH1, pX2);

    gemm64<<<dim3(8, 32), 256>>>(pX2, W1, b1, nullptr, pG, HID, DMODEL, 1);
    gemm64<<<dim3(4, 32), 256>>>(pG, W2, b2, pH1, out, DMODEL, HID, 0);
}

// round 3
// speedup vs baseline: 2.8892x; 2.7034x over previous
#include <cuda_runtime.h>
#include <cuda_bf16.h>
#include <math.h>

#define N_NODES 2048
#define DMODEL  256
#define NHEAD   8
#define DK      32
#define NEDGE   65536
#define HID     512

typedef unsigned long long ull;
typedef unsigned int u32;

// ---- packed f32x2 helpers ----
__device__ __forceinline__ ull fma2(ull a, ull b, ull c) {
    ull d; asm("fma.rn.f32x2 %0,%1,%2,%3;" : "=l"(d) : "l"(a), "l"(b), "l"(c)); return d;
}
__device__ __forceinline__ ull pack2(float x, float y) {
    ull r; asm("mov.b64 %0,{%1,%2};" : "=l"(r) : "f"(x), "f"(y)); return r;
}
__device__ __forceinline__ float2 unpack2(ull v) {
    float x, y; asm("mov.b64 {%0,%1},%2;" : "=f"(x), "=f"(y) : "l"(v));
    return make_float2(x, y);
}
// ---- mma / ldmatrix helpers ----
__device__ __forceinline__ u32 su32(const void* p) {
    return (u32)__cvta_generic_to_shared(p);
}
__device__ __forceinline__ void ldsm_x4(u32& r0, u32& r1, u32& r2, u32& r3, u32 a) {
    asm volatile("ldmatrix.sync.aligned.m8n8.x4.shared.b16 {%0,%1,%2,%3},[%4];"
                 : "=r"(r0), "=r"(r1), "=r"(r2), "=r"(r3) : "r"(a));
}
__device__ __forceinline__ void ldsm_x4t(u32& r0, u32& r1, u32& r2, u32& r3, u32 a) {
    asm volatile("ldmatrix.sync.aligned.m8n8.x4.trans.shared.b16 {%0,%1,%2,%3},[%4];"
                 : "=r"(r0), "=r"(r1), "=r"(r2), "=r"(r3) : "r"(a));
}
__device__ __forceinline__ void mma16816(float& c0, float& c1, float& c2, float& c3,
                                         u32 a0, u32 a1, u32 a2, u32 a3, u32 b0, u32 b1) {
    asm volatile("mma.sync.aligned.m16n8k16.row.col.f32.bf16.bf16.f32 "
                 "{%0,%1,%2,%3},{%4,%5,%6,%7},{%8,%9},{%0,%1,%2,%3};"
                 : "+f"(c0), "+f"(c1), "+f"(c2), "+f"(c3)
                 : "r"(a0), "r"(a1), "r"(a2), "r"(a3), "r"(b0), "r"(b1));
}
__device__ __forceinline__ float ex2f(float x) {
    float r; asm("ex2.approx.f32 %0,%1;" : "=f"(r) : "f"(x)); return r;
}
__device__ __forceinline__ u32 cvt2bf(float hi, float lo) {
    u32 r; asm("cvt.rn.bf16x2.f32 %0,%1,%2;" : "=r"(r) : "f"(hi), "f"(lo)); return r;
}

// ---------------- scratch ----------------
__device__ __nv_bfloat16 g_Qb[N_NODES * DMODEL];
__device__ __nv_bfloat16 g_Kb[N_NODES * DMODEL];
__device__ __nv_bfloat16 g_Vb[N_NODES * DMODEL];
__device__ float g_eb[NEDGE * NHEAD];       // pre-scaled by log2(e)
__device__ int   g_win[N_NODES * N_NODES];
__device__ float g_attn[N_NODES * DMODEL];
__device__ float g_Y[N_NODES * DMODEL];
__device__ float g_h1[N_NODES * DMODEL];
__device__ float g_x2[N_NODES * DMODEL];
__device__ float g_G[N_NODES * HID];

// ---------------- reset winner map ----------------
__global__ __launch_bounds__(1024) void reset_winner_kernel() {
    int i = blockIdx.x * blockDim.x + threadIdx.x;
    ((int4*)g_win)[i] = make_int4(-1, -1, -1, -1);
}

// ---------------- edge bias (log2e-scaled) + scatter winner ----------------
__global__ __launch_bounds__(256) void edge_kernel(const float* __restrict__ ea,
                                                   const float* __restrict__ We,
                                                   const float* __restrict__ be,
                                                   const int*   __restrict__ eidx) {
    const float L2E = 1.4426950408889634f;
    int e = blockIdx.x * blockDim.x + threadIdx.x;
    float a[7];
#pragma unroll
    for (int j = 0; j < 7; j++) a[j] = ea[e * 7 + j];
#pragma unroll
    for (int hh = 0; hh < 8; hh++) {
        float v = be[hh];
#pragma unroll
        for (int j = 0; j < 7; j++) v += a[j] * We[j * 8 + hh];
        g_eb[e * 8 + hh] = v * L2E;
    }
    int src = eidx[e];
    int dst = eidx[NEDGE + e];
    atomicMax(&g_win[src * N_NODES + dst], e);
}

// ---------------- SGEMM body: 64x64 tile, BK=16, 256 threads, f32x2 math ----------
__device__ __forceinline__ void gemm_body(const float* __restrict__ A,
                                          const float* __restrict__ B,
                                          const float* __restrict__ bias,
                                          const float* __restrict__ R,
                                          float* __restrict__ C,
                                          __nv_bfloat16* __restrict__ Cb,
                                          int N, int K, int gelu,
                                          int bm, int bn) {
    __shared__ float As[16][68];
    __shared__ float Bs[16][68];
    const int tid = threadIdx.x;
    const int tn = tid & 15, tm = tid >> 4;
    const int arow = tid >> 2, acol = (tid & 3) << 2;
    const int brow = tid >> 4, bcol = (tid & 15) << 2;
    const float* Aptr = A + (size_t)(bm + arow) * K + acol;
    const float* Bptr = B + (size_t)brow * N + bn + bcol;
    ull acc[4][2];
#pragma unroll
    for (int i = 0; i < 4; i++) { acc[i][0] = 0ull; acc[i][1] = 0ull; }

    for (int k0 = 0; k0 < K; k0 += 16) {
        float4 a4 = *(const float4*)(Aptr + k0);
        float4 b4 = *(const float4*)(Bptr + (size_t)k0 * N);
        __syncthreads();
        As[acol + 0][arow] = a4.x;
        As[acol + 1][arow] = a4.y;
        As[acol + 2][arow] = a4.z;
        As[acol + 3][arow] = a4.w;
        *(float4*)&Bs[brow][bcol] = b4;
        __syncthreads();
#pragma unroll
        for (int kk = 0; kk < 16; kk++) {
            float4 av = *(const float4*)&As[kk][tm << 2];
            ulonglong2 bv = *(const ulonglong2*)&Bs[kk][tn << 2];
            ull a0 = pack2(av.x, av.x);
            ull a1 = pack2(av.y, av.y);
            ull a2 = pack2(av.z, av.z);
            ull a3 = pack2(av.w, av.w);
            acc[0][0] = fma2(a0, bv.x, acc[0][0]); acc[0][1] = fma2(a0, bv.y, acc[0][1]);
            acc[1][0] = fma2(a1, bv.x, acc[1][0]); acc[1][1] = fma2(a1, bv.y, acc[1][1]);
            acc[2][0] = fma2(a2, bv.x, acc[2][0]); acc[2][1] = fma2(a2, bv.y, acc[2][1]);
            acc[3][0] = fma2(a3, bv.x, acc[3][0]); acc[3][1] = fma2(a3, bv.y, acc[3][1]);
        }
    }

    const int crow = bm + (tm << 2), ccol = bn + (tn << 2);
#pragma unroll
    for (int i = 0; i < 4; i++) {
        float2 u0 = unpack2(acc[i][0]);
        float2 u1 = unpack2(acc[i][1]);
        float o[4] = {u0.x, u0.y, u1.x, u1.y};
#pragma unroll
        for (int j = 0; j < 4; j++) {
            float v = o[j] + bias[ccol + j];
            if (gelu) v = v * normcdff(v);
            if (R) v += R[(size_t)(crow + i) * N + ccol + j];
            o[j] = v;
        }
        if (Cb) {
            uint2 p;
            p.x = cvt2bf(o[1], o[0]);
            p.y = cvt2bf(o[3], o[2]);
            *(uint2*)&Cb[(size_t)(crow + i) * N + ccol] = p;
        } else {
            *(float4*)&C[(size_t)(crow + i) * N + ccol] =
                make_float4(o[0], o[1], o[2], o[3]);
        }
    }
}

__global__ __launch_bounds__(256) void gemm64(const float* __restrict__ A,
                                              const float* __restrict__ B,
                                              const float* __restrict__ bias,
                                              const float* __restrict__ R,
                                              float* __restrict__ C,
                                              int N, int K, int gelu) {
    gemm_body(A, B, bias, R, C, nullptr, N, K, gelu, blockIdx.y * 64, blockIdx.x * 64);
}

// fused QKV -> bf16 outputs
__global__ __launch_bounds__(256) void gemm_qkv(const float* __restrict__ A,
                                                const float* __restrict__ Wq,
                                                const float* __restrict__ bq,
                                                const float* __restrict__ Wk,
                                                const float* __restrict__ bk,
                                                const float* __restrict__ Wv,
                                                const float* __restrict__ bv) {
    int sel = blockIdx.x >> 2;
    int bn  = (blockIdx.x & 3) * 64;
    const float* B    = (sel == 0) ? Wq : (sel == 1) ? Wk : Wv;
    const float* bias = (sel == 0) ? bq : (sel == 1) ? bk : bv;
    __nv_bfloat16* Cb = (sel == 0) ? g_Qb : (sel == 1) ? g_Kb : g_Vb;
    gemm_body(A, B, bias, nullptr, nullptr, Cb, DMODEL, DMODEL, 0, blockIdx.y * 64, bn);
}

// ---------------- tensor-core flash attention ----------------
// block = 128 threads (4 warps), 64 queries, 1 head. 64-key tiles, mma.sync bf16.
__global__ __launch_bounds__(128, 3) void attn_mma(const __nv_bfloat16* __restrict__ Qb,
                                                   const __nv_bfloat16* __restrict__ Kb,
                                                   const __nv_bfloat16* __restrict__ Vb,
                                                   float* __restrict__ Out) {
    __shared__ __align__(16) __nv_bfloat16 Ks[64][40];   // 80B rows: conflict-free ldmatrix
    __shared__ __align__(16) __nv_bfloat16 Vs[64][40];

    const int h   = blockIdx.y;
    const int qb  = blockIdx.x * 64;
    const int tid = threadIdx.x;
    const int warp = tid >> 5, lane = tid & 31;

    // ---- stage Q tile into Ks, build per-warp A-fragments ----
#pragma unroll
    for (int i = 0; i < 2; i++) {
        int task = tid + 128 * i;
        int row = task >> 2, ch = task & 3;
        uint4 v = *(const uint4*)((const char*)(Qb + (size_t)(qb + row) * DMODEL + h * DK) + ch * 16);
        *(uint4*)((char*)&Ks[row][0] + ch * 16) = v;
    }
    __syncthreads();
    const int lr = lane & 7, lm = lane >> 3;
    u32 qa[2][4];
    {
        int row = warp * 16 + lr + (lm & 1) * 8;
#pragma unroll
        for (int c = 0; c < 2; c++) {
            u32 a = su32(&Ks[row][c * 16 + (lm >> 1) * 8]);
            ldsm_x4(qa[c][0], qa[c][1], qa[c][2], qa[c][3], a);
        }
    }
    __syncthreads();

    // ldmatrix base addresses
    const u32 kaddr = su32(&Ks[lr][lm * 8]);                               // + kg*640
    const u32 vaddr = su32(&Vs[lr + (lm & 1) * 8][(lm >> 1) * 8]);         // + c*1280 + tp*32

    float O[4][4];
#pragma unroll
    for (int t = 0; t < 4; t++)
#pragma unroll
        for (int j = 0; j < 4; j++) O[t][j] = 0.f;
    float l0 = 0.f, l1 = 0.f;

    const float SCALE2 = 1.4426950408889634f * 0.17677669529663688f;
    const int r0 = qb + warp * 16 + (lane >> 2);
    const int r1 = r0 + 8;
    const int cql = 2 * (lane & 3);

    for (int kt = 0; kt < N_NODES / 64; kt++) {
        const int kb = kt * 64;
        // prefetch K/V tile chunks
        uint4 pk[2], pv[2];
#pragma unroll
        for (int i = 0; i < 2; i++) {
            int task = tid + 128 * i;
            int row = task >> 2, ch = task & 3;
            const char* kp = (const char*)(Kb + (size_t)(kb + row) * DMODEL + h * DK) + ch * 16;
            const char* vp = (const char*)(Vb + (size_t)(kb + row) * DMODEL + h * DK) + ch * 16;
            pk[i] = *(const uint4*)kp;
            pv[i] = *(const uint4*)vp;
        }
        __syncthreads();
#pragma unroll
        for (int i = 0; i < 2; i++) {
            int task = tid + 128 * i;
            int row = task >> 2, ch = task & 3;
            *(uint4*)((char*)&Ks[row][0] + ch * 16) = pk[i];
            *(uint4*)((char*)&Vs[row][0] + ch * 16) = pv[i];
        }
        __syncthreads();

        // ---- scores + exp -> packed bf16 P frags ----
        u32 P[8][2];
#pragma unroll
        for (int kg = 0; kg < 8; kg++) {
            u32 b0, b1, b2, b3;
            ldsm_x4(b0, b1, b2, b3, kaddr + kg * 640);
            float c0 = 0.f, c1 = 0.f, c2 = 0.f, c3 = 0.f;
            mma16816(c0, c1, c2, c3, qa[0][0], qa[0][1], qa[0][2], qa[0][3], b0, b1);
            mma16816(c0, c1, c2, c3, qa[1][0], qa[1][1], qa[1][2], qa[1][3], b2, b3);

            int colb = kb + kg * 8 + cql;
            int2 w0 = *(const int2*)&g_win[(size_t)r0 * N_NODES + colb];
            int2 w1 = *(const int2*)&g_win[(size_t)r1 * N_NODES + colb];
            float e00 = (w0.x >= 0) ? g_eb[(size_t)w0.x * 8 + h] : 0.f;
            float e01 = (w0.y >= 0) ? g_eb[(size_t)w0.y * 8 + h] : 0.f;
            float e10 = (w1.x >= 0) ? g_eb[(size_t)w1.x * 8 + h] : 0.f;
            float e11 = (w1.y >= 0) ? g_eb[(size_t)w1.y * 8 + h] : 0.f;
            float p0 = ex2f(fmaf(c0, SCALE2, e00));
            float p1 = ex2f(fmaf(c1, SCALE2, e01));
            float p2 = ex2f(fmaf(c2, SCALE2, e10));
            float p3 = ex2f(fmaf(c3, SCALE2, e11));
            l0 += p0 + p1;
            l1 += p2 + p3;
            P[kg][0] = cvt2bf(p1, p0);
            P[kg][1] = cvt2bf(p3, p2);
        }

        // ---- PV ----
#pragma unroll
        for (int ck = 0; ck < 4; ck++) {
            u32 a0 = P[2 * ck][0], a1 = P[2 * ck][1];
            u32 a2 = P[2 * ck + 1][0], a3 = P[2 * ck + 1][1];
#pragma unroll
            for (int tp = 0; tp < 2; tp++) {
                u32 v0, v1, v2, v3;
                ldsm_x4t(v0, v1, v2, v3, vaddr + ck * 1280 + tp * 32);
                mma16816(O[2 * tp][0], O[2 * tp][1], O[2 * tp][2], O[2 * tp][3],
                         a0, a1, a2, a3, v0, v1);
                mma16816(O[2 * tp + 1][0], O[2 * tp + 1][1], O[2 * tp + 1][2], O[2 * tp + 1][3],
                         a0, a1, a2, a3, v2, v3);
            }
        }
    }

    // reduce softmax denominators across the 4 lanes sharing each row
    l0 += __shfl_xor_sync(0xffffffffu, l0, 1);
    l0 += __shfl_xor_sync(0xffffffffu, l0, 2);
    l1 += __shfl_xor_sync(0xffffffffu, l1, 1);
    l1 += __shfl_xor_sync(0xffffffffu, l1, 2);
    float inv0 = 1.f / l0, inv1 = 1.f / l1;

#pragma unroll
    for (int t = 0; t < 4; t++) {
        int col = h * DK + t * 8 + cql;
        *(float2*)&Out[(size_t)r0 * DMODEL + col] = make_float2(O[t][0] * inv0, O[t][1] * inv0);
        *(float2*)&Out[(size_t)r1 * DMODEL + col] = make_float2(O[t][2] * inv1, O[t][3] * inv1);
    }
}

// ---------------- fused double LayerNorm ----------------
__global__ __launch_bounds__(256) void ln_kernel(const float* __restrict__ Y,
                                                 const float* __restrict__ g1,
                                                 const float* __restrict__ b1,
                                                 const float* __restrict__ g2,
                                                 const float* __restrict__ b2,
                                                 float* __restrict__ H1,
                                                 float* __restrict__ X2) {
    const int lane = threadIdx.x & 31;
    const int row  = blockIdx.x * 8 + (threadIdx.x >> 5);
    const float* y = Y + (size_t)row * DMODEL;
    float v[8];
#pragma unroll
    for (int j = 0; j < 8; j++) v[j] = y[lane + 32 * j];

    float s = 0.f;
#pragma unroll
    for (int j = 0; j < 8; j++) s += v[j];
#pragma unroll
    for (int o = 16; o; o >>= 1) s += __shfl_xor_sync(0xffffffffu, s, o);
    float mu = s * (1.f / 256.f);
    float q = 0.f;
#pragma unroll
    for (int j = 0; j < 8; j++) { float d = v[j] - mu; q += d * d; }
#pragma unroll
    for (int o = 16; o; o >>= 1) q += __shfl_xor_sync(0xffffffffu, q, o);
    float rs = rsqrtf(q * (1.f / 256.f) + 1e-5f);

    float hv[8];
#pragma unroll
    for (int j = 0; j < 8; j++) {
        int c = lane + 32 * j;
        hv[j] = (v[j] - mu) * rs * g1[c] + b1[c];
        H1[(size_t)row * DMODEL + c] = hv[j];
    }

    s = 0.f;
#pragma unroll
    for (int j = 0; j < 8; j++) s += hv[j];
#pragma unroll
    for (int o = 16; o; o >>= 1) s += __shfl_xor_sync(0xffffffffu, s, o);
    mu = s * (1.f / 256.f);
    q = 0.f;
#pragma unroll
    for (int j = 0; j < 8; j++) { float d = hv[j] - mu; q += d * d; }
#pragma unroll
    for (int o = 16; o; o >>= 1) q += __shfl_xor_sync(0xffffffffu, q, o);
    rs = rsqrtf(q * (1.f / 256.f) + 1e-5f);
#pragma unroll
    for (int j = 0; j < 8; j++) {
        int c = lane + 32 * j;
        X2[(size_t)row * DMODEL + c] = (hv[j] - mu) * rs * g2[c] + b2[c];
    }
}

// ---------------- launch ----------------
extern "C" void kernel_launch(void* const* d_in, const int* in_sizes, int n_in,
                              void* d_out, int out_size) {
    const float* h    = (const float*)d_in[0];
    const float* ea   = (const float*)d_in[1];
    const float* Wq   = (const float*)d_in[2];
    const float* bq   = (const float*)d_in[3];
    const float* Wk   = (const float*)d_in[4];
    const float* bk   = (const float*)d_in[5];
    const float* Wv   = (const float*)d_in[6];
    const float* bv   = (const float*)d_in[7];
    const float* Wo   = (const float*)d_in[8];
    const float* bo   = (const float*)d_in[9];
    const float* We   = (const float*)d_in[10];
    const float* be   = (const float*)d_in[11];
    const float* ln1g = (const float*)d_in[12];
    const float* ln1b = (const float*)d_in[13];
    const float* flng = (const float*)d_in[14];
    const float* flnb = (const float*)d_in[15];
    const float* W1   = (const float*)d_in[16];
    const float* b1   = (const float*)d_in[17];
    const float* W2   = (const float*)d_in[18];
    const float* b2   = (const float*)d_in[19];
    const int*   eidx = (const int*)d_in[20];
    float* out = (float*)d_out;

    __nv_bfloat16 *pQb, *pKb, *pVb;
    float *pAttn, *pY, *pH1, *pX2, *pG;
    cudaGetSymbolAddress((void**)&pQb,   g_Qb);
    cudaGetSymbolAddress((void**)&pKb,   g_Kb);
    cudaGetSymbolAddress((void**)&pVb,   g_Vb);
    cudaGetSymbolAddress((void**)&pAttn, g_attn);
    cudaGetSymbolAddress((void**)&pY,    g_Y);
    cudaGetSymbolAddress((void**)&pH1,   g_h1);
    cudaGetSymbolAddress((void**)&pX2,   g_x2);
    cudaGetSymbolAddress((void**)&pG,    g_G);

    reset_winner_kernel<<<1024, 1024>>>();
    edge_kernel<<<NEDGE / 256, 256>>>(ea, We, be, eidx);

    gemm_qkv<<<dim3(12, 32), 256>>>(h, Wq, bq, Wk, bk, Wv, bv);

    attn_mma<<<dim3(N_NODES / 64, NHEAD), 128>>>(pQb, pKb, pVb, pAttn);

    gemm64<<<dim3(4, 32), 256>>>(pAttn, Wo, bo, h, pY, DMODEL, DMODEL, 0);

    ln_kernel<<<N_NODES / 8, 256>>>(pY, ln1g, ln1b, flng, flnb, pH1, pX2);

    gemm64<<<dim3(8, 32), 256>>>(pX2, W1, b1, nullptr, pG, HID, DMODEL, 1);
    gemm64<<<dim3(4, 32), 256>>>(pG, W2, b2, pH1, out, DMODEL, HID, 0);
}

// round 4
// speedup vs baseline: 3.0871x; 1.0685x over previous
#include <cuda_runtime.h>
#include <cuda_bf16.h>
#include <math.h>

#define N_NODES 2048
#define DMODEL  256
#define NHEAD   8
#define DK      32
#define NEDGE   65536
#define HID     512
#define KSPLIT  4

typedef unsigned long long ull;
typedef unsigned int u32;

// ---- packed f32x2 helpers ----
__device__ __forceinline__ ull fma2(ull a, ull b, ull c) {
    ull d; asm("fma.rn.f32x2 %0,%1,%2,%3;" : "=l"(d) : "l"(a), "l"(b), "l"(c)); return d;
}
__device__ __forceinline__ ull pack2(float x, float y) {
    ull r; asm("mov.b64 %0,{%1,%2};" : "=l"(r) : "f"(x), "f"(y)); return r;
}
__device__ __forceinline__ float2 unpack2(ull v) {
    float x, y; asm("mov.b64 {%0,%1},%2;" : "=f"(x), "=f"(y) : "l"(v));
    return make_float2(x, y);
}
// ---- mma / ldmatrix helpers ----
__device__ __forceinline__ u32 su32(const void* p) {
    return (u32)__cvta_generic_to_shared(p);
}
__device__ __forceinline__ void ldsm_x4(u32& r0, u32& r1, u32& r2, u32& r3, u32 a) {
    asm volatile("ldmatrix.sync.aligned.m8n8.x4.shared.b16 {%0,%1,%2,%3},[%4];"
                 : "=r"(r0), "=r"(r1), "=r"(r2), "=r"(r3) : "r"(a));
}
__device__ __forceinline__ void ldsm_x4t(u32& r0, u32& r1, u32& r2, u32& r3, u32 a) {
    asm volatile("ldmatrix.sync.aligned.m8n8.x4.trans.shared.b16 {%0,%1,%2,%3},[%4];"
                 : "=r"(r0), "=r"(r1), "=r"(r2), "=r"(r3) : "r"(a));
}
__device__ __forceinline__ void mma16816(float& c0, float& c1, float& c2, float& c3,
                                         u32 a0, u32 a1, u32 a2, u32 a3, u32 b0, u32 b1) {
    asm volatile("mma.sync.aligned.m16n8k16.row.col.f32.bf16.bf16.f32 "
                 "{%0,%1,%2,%3},{%4,%5,%6,%7},{%8,%9},{%0,%1,%2,%3};"
                 : "+f"(c0), "+f"(c1), "+f"(c2), "+f"(c3)
                 : "r"(a0), "r"(a1), "r"(a2), "r"(a3), "r"(b0), "r"(b1));
}
__device__ __forceinline__ float ex2f(float x) {
    float r; asm("ex2.approx.f32 %0,%1;" : "=f"(r) : "f"(x)); return r;
}
__device__ __forceinline__ u32 cvt2bf(float hi, float lo) {
    u32 r; asm("cvt.rn.bf16x2.f32 %0,%1,%2;" : "=r"(r) : "f"(hi), "f"(lo)); return r;
}

// ---------------- scratch ----------------
__device__ __nv_bfloat16 g_Qb[N_NODES * DMODEL];
__device__ __nv_bfloat16 g_Kb[N_NODES * DMODEL];
__device__ __nv_bfloat16 g_Vb[N_NODES * DMODEL];
__device__ float g_eb[NEDGE * NHEAD];            // pre-scaled by log2(e)
__device__ int   g_win[N_NODES * N_NODES];
__device__ float g_part[KSPLIT * N_NODES * DMODEL];   // unnormalized O partials
__device__ float g_lp[KSPLIT * N_NODES * NHEAD];      // softmax-denominator partials
__device__ float g_attn[N_NODES * DMODEL];
__device__ float g_Y[N_NODES * DMODEL];
__device__ float g_h1[N_NODES * DMODEL];
__device__ float g_x2[N_NODES * DMODEL];
__device__ float g_G[N_NODES * HID];

// ---------------- reset winner map ----------------
__global__ __launch_bounds__(1024) void reset_winner_kernel() {
    int i = blockIdx.x * blockDim.x + threadIdx.x;
    ((int4*)g_win)[i] = make_int4(-1, -1, -1, -1);
}

// ---------------- edge bias (log2e-scaled) + scatter winner ----------------
__global__ __launch_bounds__(256) void edge_kernel(const float* __restrict__ ea,
                                                   const float* __restrict__ We,
                                                   const float* __restrict__ be,
                                                   const int*   __restrict__ eidx) {
    const float L2E = 1.4426950408889634f;
    int e = blockIdx.x * blockDim.x + threadIdx.x;
    float a[7];
#pragma unroll
    for (int j = 0; j < 7; j++) a[j] = ea[e * 7 + j];
#pragma unroll
    for (int hh = 0; hh < 8; hh++) {
        float v = be[hh];
#pragma unroll
        for (int j = 0; j < 7; j++) v += a[j] * We[j * 8 + hh];
        g_eb[e * 8 + hh] = v * L2E;
    }
    int src = eidx[e];
    int dst = eidx[NEDGE + e];
    atomicMax(&g_win[src * N_NODES + dst], e);
}

// ---------------- SGEMM body: 64x64 tile, BK=16, 256 threads, f32x2 math ----------
__device__ __forceinline__ void gemm_body(const float* __restrict__ A,
                                          const float* __restrict__ B,
                                          const float* __restrict__ bias,
                                          const float* __restrict__ R,
                                          float* __restrict__ C,
                                          __nv_bfloat16* __restrict__ Cb,
                                          int N, int K, int gelu,
                                          int bm, int bn) {
    __shared__ float As[16][68];
    __shared__ float Bs[16][68];
    const int tid = threadIdx.x;
    const int tn = tid & 15, tm = tid >> 4;
    const int arow = tid >> 2, acol = (tid & 3) << 2;
    const int brow = tid >> 4, bcol = (tid & 15) << 2;
    const float* Aptr = A + (size_t)(bm + arow) * K + acol;
    const float* Bptr = B + (size_t)brow * N + bn + bcol;
    ull acc[4][2];
#pragma unroll
    for (int i = 0; i < 4; i++) { acc[i][0] = 0ull; acc[i][1] = 0ull; }

    for (int k0 = 0; k0 < K; k0 += 16) {
        float4 a4 = *(const float4*)(Aptr + k0);
        float4 b4 = *(const float4*)(Bptr + (size_t)k0 * N);
        __syncthreads();
        As[acol + 0][arow] = a4.x;
        As[acol + 1][arow] = a4.y;
        As[acol + 2][arow] = a4.z;
        As[acol + 3][arow] = a4.w;
        *(float4*)&Bs[brow][bcol] = b4;
        __syncthreads();
#pragma unroll
        for (int kk = 0; kk < 16; kk++) {
            float4 av = *(const float4*)&As[kk][tm << 2];
            ulonglong2 bv = *(const ulonglong2*)&Bs[kk][tn << 2];
            ull a0 = pack2(av.x, av.x);
            ull a1 = pack2(av.y, av.y);
            ull a2 = pack2(av.z, av.z);
            ull a3 = pack2(av.w, av.w);
            acc[0][0] = fma2(a0, bv.x, acc[0][0]); acc[0][1] = fma2(a0, bv.y, acc[0][1]);
            acc[1][0] = fma2(a1, bv.x, acc[1][0]); acc[1][1] = fma2(a1, bv.y, acc[1][1]);
            acc[2][0] = fma2(a2, bv.x, acc[2][0]); acc[2][1] = fma2(a2, bv.y, acc[2][1]);
            acc[3][0] = fma2(a3, bv.x, acc[3][0]); acc[3][1] = fma2(a3, bv.y, acc[3][1]);
        }
    }

    const int crow = bm + (tm << 2), ccol = bn + (tn << 2);
#pragma unroll
    for (int i = 0; i < 4; i++) {
        float2 u0 = unpack2(acc[i][0]);
        float2 u1 = unpack2(acc[i][1]);
        float o[4] = {u0.x, u0.y, u1.x, u1.y};
#pragma unroll
        for (int j = 0; j < 4; j++) {
            float v = o[j] + bias[ccol + j];
            if (gelu) v = v * normcdff(v);
            if (R) v += R[(size_t)(crow + i) * N + ccol + j];
            o[j] = v;
        }
        if (Cb) {
            uint2 p;
            p.x = cvt2bf(o[1], o[0]);
            p.y = cvt2bf(o[3], o[2]);
            *(uint2*)&Cb[(size_t)(crow + i) * N + ccol] = p;
        } else {
            *(float4*)&C[(size_t)(crow + i) * N + ccol] =
                make_float4(o[0], o[1], o[2], o[3]);
        }
    }
}

__global__ __launch_bounds__(256) void gemm64(const float* __restrict__ A,
                                              const float* __restrict__ B,
                                              const float* __restrict__ bias,
                                              const float* __restrict__ R,
                                              float* __restrict__ C,
                                              int N, int K, int gelu) {
    gemm_body(A, B, bias, R, C, nullptr, N, K, gelu, blockIdx.y * 64, blockIdx.x * 64);
}

// fused QKV -> bf16 outputs
__global__ __launch_bounds__(256) void gemm_qkv(const float* __restrict__ A,
                                                const float* __restrict__ Wq,
                                                const float* __restrict__ bq,
                                                const float* __restrict__ Wk,
                                                const float* __restrict__ bk,
                                                const float* __restrict__ Wv,
                                                const float* __restrict__ bv) {
    int sel = blockIdx.x >> 2;
    int bn  = (blockIdx.x & 3) * 64;
    const float* B    = (sel == 0) ? Wq : (sel == 1) ? Wk : Wv;
    const float* bias = (sel == 0) ? bq : (sel == 1) ? bk : bv;
    __nv_bfloat16* Cb = (sel == 0) ? g_Qb : (sel == 1) ? g_Kb : g_Vb;
    gemm_body(A, B, bias, nullptr, nullptr, Cb, DMODEL, DMODEL, 0, blockIdx.y * 64, bn);
}

// ---------------- tensor-core flash attention, split-K ----------------
// block = 128 threads (4 warps), 64 queries, 1 head, 512-key chunk.
// grid = (32 qtiles, 8 heads, KSPLIT chunks). Writes unnormalized partials.
__global__ __launch_bounds__(128, 4) void attn_mma(const __nv_bfloat16* __restrict__ Qb,
                                                   const __nv_bfloat16* __restrict__ Kb,
                                                   const __nv_bfloat16* __restrict__ Vb) {
    __shared__ __align__(16) __nv_bfloat16 Ks[64][40];   // 80B rows: conflict-free ldmatrix
    __shared__ __align__(16) __nv_bfloat16 Vs[64][40];

    const int h     = blockIdx.y;
    const int qb    = blockIdx.x * 64;
    const int chunk = blockIdx.z;
    const int kb0   = chunk * (N_NODES / KSPLIT);
    const int tid = threadIdx.x;
    const int warp = tid >> 5, lane = tid & 31;

    // ---- stage Q tile into Ks, build per-warp A-fragments ----
#pragma unroll
    for (int i = 0; i < 2; i++) {
        int task = tid + 128 * i;
        int row = task >> 2, ch = task & 3;
        uint4 v = *(const uint4*)((const char*)(Qb + (size_t)(qb + row) * DMODEL + h * DK) + ch * 16);
        *(uint4*)((char*)&Ks[row][0] + ch * 16) = v;
    }
    __syncthreads();
    const int lr = lane & 7, lm = lane >> 3;
    u32 qa[2][4];
    {
        int row = warp * 16 + lr + (lm & 1) * 8;
#pragma unroll
        for (int c = 0; c < 2; c++) {
            u32 a = su32(&Ks[row][c * 16 + (lm >> 1) * 8]);
            ldsm_x4(qa[c][0], qa[c][1], qa[c][2], qa[c][3], a);
        }
    }

    // ldmatrix base addresses
    const u32 kaddr = su32(&Ks[lr][lm * 8]);                               // + kg*640
    const u32 vaddr = su32(&Vs[lr + (lm & 1) * 8][(lm >> 1) * 8]);         // + c*1280 + tp*32

    float O[4][4];
#pragma unroll
    for (int t = 0; t < 4; t++)
#pragma unroll
        for (int j = 0; j < 4; j++) O[t][j] = 0.f;
    float l0 = 0.f, l1 = 0.f;

    const float SCALE2 = 1.4426950408889634f * 0.17677669529663688f;
    const int r0 = qb + warp * 16 + (lane >> 2);
    const int r1 = r0 + 8;
    const int cql = 2 * (lane & 3);

    for (int kt = 0; kt < (N_NODES / KSPLIT) / 64; kt++) {
        const int kb = kb0 + kt * 64;
        __syncthreads();
#pragma unroll
        for (int i = 0; i < 2; i++) {
            int task = tid + 128 * i;
            int row = task >> 2, ch = task & 3;
            const char* kp = (const char*)(Kb + (size_t)(kb + row) * DMODEL + h * DK) + ch * 16;
            const char* vp = (const char*)(Vb + (size_t)(kb + row) * DMODEL + h * DK) + ch * 16;
            *(uint4*)((char*)&Ks[row][0] + ch * 16) = *(const uint4*)kp;
            *(uint4*)((char*)&Vs[row][0] + ch * 16) = *(const uint4*)vp;
        }
        __syncthreads();

        // ---- scores + exp -> packed bf16 P frags ----
        u32 P[8][2];
#pragma unroll
        for (int kg = 0; kg < 8; kg++) {
            u32 b0, b1, b2, b3;
            ldsm_x4(b0, b1, b2, b3, kaddr + kg * 640);
            float c0 = 0.f, c1 = 0.f, c2 = 0.f, c3 = 0.f;
            mma16816(c0, c1, c2, c3, qa[0][0], qa[0][1], qa[0][2], qa[0][3], b0, b1);
            mma16816(c0, c1, c2, c3, qa[1][0], qa[1][1], qa[1][2], qa[1][3], b2, b3);

            int colb = kb + kg * 8 + cql;
            int2 w0 = *(const int2*)&g_win[(size_t)r0 * N_NODES + colb];
            int2 w1 = *(const int2*)&g_win[(size_t)r1 * N_NODES + colb];
            float e00 = (w0.x >= 0) ? g_eb[(size_t)w0.x * 8 + h] : 0.f;
            float e01 = (w0.y >= 0) ? g_eb[(size_t)w0.y * 8 + h] : 0.f;
            float e10 = (w1.x >= 0) ? g_eb[(size_t)w1.x * 8 + h] : 0.f;
            float e11 = (w1.y >= 0) ? g_eb[(size_t)w1.y * 8 + h] : 0.f;
            float p0 = ex2f(fmaf(c0, SCALE2, e00));
            float p1 = ex2f(fmaf(c1, SCALE2, e01));
            float p2 = ex2f(fmaf(c2, SCALE2, e10));
            float p3 = ex2f(fmaf(c3, SCALE2, e11));
            l0 += p0 + p1;
            l1 += p2 + p3;
            P[kg][0] = cvt2bf(p1, p0);
            P[kg][1] = cvt2bf(p3, p2);
        }

        // ---- PV ----
#pragma unroll
        for (int ck = 0; ck < 4; ck++) {
            u32 a0 = P[2 * ck][0], a1 = P[2 * ck][1];
            u32 a2 = P[2 * ck + 1][0], a3 = P[2 * ck + 1][1];
#pragma unroll
            for (int tp = 0; tp < 2; tp++) {
                u32 v0, v1, v2, v3;
                ldsm_x4t(v0, v1, v2, v3, vaddr + ck * 1280 + tp * 32);
                mma16816(O[2 * tp][0], O[2 * tp][1], O[2 * tp][2], O[2 * tp][3],
                         a0, a1, a2, a3, v0, v1);
                mma16816(O[2 * tp + 1][0], O[2 * tp + 1][1], O[2 * tp + 1][2], O[2 * tp + 1][3],
                         a0, a1, a2, a3, v2, v3);
            }
        }
    }

    // reduce partial denominators across the 4 lanes sharing each row
    l0 += __shfl_xor_sync(0xffffffffu, l0, 1);
    l0 += __shfl_xor_sync(0xffffffffu, l0, 2);
    l1 += __shfl_xor_sync(0xffffffffu, l1, 1);
    l1 += __shfl_xor_sync(0xffffffffu, l1, 2);

    float* part = g_part + (size_t)chunk * N_NODES * DMODEL;
#pragma unroll
    for (int t = 0; t < 4; t++) {
        int col = h * DK + t * 8 + cql;
        *(float2*)&part[(size_t)r0 * DMODEL + col] = make_float2(O[t][0], O[t][1]);
        *(float2*)&part[(size_t)r1 * DMODEL + col] = make_float2(O[t][2], O[t][3]);
    }
    if ((lane & 3) == 0) {
        g_lp[((size_t)chunk * N_NODES + r0) * NHEAD + h] = l0;
        g_lp[((size_t)chunk * N_NODES + r1) * NHEAD + h] = l1;
    }
}

// ---------------- combine split-K partials (deterministic) ----------------
__global__ __launch_bounds__(256) void combine_kernel() {
    int gid = blockIdx.x * 256 + threadIdx.x;   // 2048*64 = 131072
    int row = gid >> 6;
    int col = (gid & 63) << 2;
    int h = col >> 5;
    float ls = 0.f;
    float4 acc = make_float4(0.f, 0.f, 0.f, 0.f);
#pragma unroll
    for (int c = 0; c < KSPLIT; c++) {
        ls += g_lp[((size_t)c * N_NODES + row) * NHEAD + h];
        float4 p = *(const float4*)&g_part[((size_t)c * N_NODES + row) * DMODEL + col];
        acc.x += p.x; acc.y += p.y; acc.z += p.z; acc.w += p.w;
    }
    float inv = 1.f / ls;
    *(float4*)&g_attn[(size_t)row * DMODEL + col] =
        make_float4(acc.x * inv, acc.y * inv, acc.z * inv, acc.w * inv);
}

// ---------------- fused double LayerNorm ----------------
__global__ __launch_bounds__(256) void ln_kernel(const float* __restrict__ Y,
                                                 const float* __restrict__ g1,
                                                 const float* __restrict__ b1,
                                                 const float* __restrict__ g2,
                                                 const float* __restrict__ b2,
                                                 float* __restrict__ H1,
                                                 float* __restrict__ X2) {
    const int lane = threadIdx.x & 31;
    const int row  = blockIdx.x * 8 + (threadIdx.x >> 5);
    const float* y = Y + (size_t)row * DMODEL;
    float v[8];
#pragma unroll
    for (int j = 0; j < 8; j++) v[j] = y[lane + 32 * j];

    float s = 0.f;
#pragma unroll
    for (int j = 0; j < 8; j++) s += v[j];
#pragma unroll
    for (int o = 16; o; o >>= 1) s += __shfl_xor_sync(0xffffffffu, s, o);
    float mu = s * (1.f / 256.f);
    float q = 0.f;
#pragma unroll
    for (int j = 0; j < 8; j++) { float d = v[j] - mu; q += d * d; }
#pragma unroll
    for (int o = 16; o; o >>= 1) q += __shfl_xor_sync(0xffffffffu, q, o);
    float rs = rsqrtf(q * (1.f / 256.f) + 1e-5f);

    float hv[8];
#pragma unroll
    for (int j = 0; j < 8; j++) {
        int c = lane + 32 * j;
        hv[j] = (v[j] - mu) * rs * g1[c] + b1[c];
        H1[(size_t)row * DMODEL + c] = hv[j];
    }

    s = 0.f;
#pragma unroll
    for (int j = 0; j < 8; j++) s += hv[j];
#pragma unroll
    for (int o = 16; o; o >>= 1) s += __shfl_xor_sync(0xffffffffu, s, o);
    mu = s * (1.f / 256.f);
    q = 0.f;
#pragma unroll
    for (int j = 0; j < 8; j++) { float d = hv[j] - mu; q += d * d; }
#pragma unroll
    for (int o = 16; o; o >>= 1) q += __shfl_xor_sync(0xffffffffu, q, o);
    rs = rsqrtf(q * (1.f / 256.f) + 1e-5f);
#pragma unroll
    for (int j = 0; j < 8; j++) {
        int c = lane + 32 * j;
        X2[(size_t)row * DMODEL + c] = (hv[j] - mu) * rs * g2[c] + b2[c];
    }
}

// ---------------- launch ----------------
extern "C" void kernel_launch(void* const* d_in, const int* in_sizes, int n_in,
                              void* d_out, int out_size) {
    const float* h    = (const float*)d_in[0];
    const float* ea   = (const float*)d_in[1];
    const float* Wq   = (const float*)d_in[2];
    const float* bq   = (const float*)d_in[3];
    const float* Wk   = (const float*)d_in[4];
    const float* bk   = (const float*)d_in[5];
    const float* Wv   = (const float*)d_in[6];
    const float* bv   = (const float*)d_in[7];
    const float* Wo   = (const float*)d_in[8];
    const float* bo   = (const float*)d_in[9];
    const float* We   = (const float*)d_in[10];
    const float* be   = (const float*)d_in[11];
    const float* ln1g = (const float*)d_in[12];
    const float* ln1b = (const float*)d_in[13];
    const float* flng = (const float*)d_in[14];
    const float* flnb = (const float*)d_in[15];
    const float* W1   = (const float*)d_in[16];
    const float* b1   = (const float*)d_in[17];
    const float* W2   = (const float*)d_in[18];
    const float* b2   = (const float*)d_in[19];
    const int*   eidx = (const int*)d_in[20];
    float* out = (float*)d_out;

    __nv_bfloat16 *pQb, *pKb, *pVb;
    float *pAttn, *pY, *pH1, *pX2, *pG;
    cudaGetSymbolAddress((void**)&pQb,   g_Qb);
    cudaGetSymbolAddress((void**)&pKb,   g_Kb);
    cudaGetSymbolAddress((void**)&pVb,   g_Vb);
    cudaGetSymbolAddress((void**)&pAttn, g_attn);
    cudaGetSymbolAddress((void**)&pY,    g_Y);
    cudaGetSymbolAddress((void**)&pH1,   g_h1);
    cudaGetSymbolAddress((void**)&pX2,   g_x2);
    cudaGetSymbolAddress((void**)&pG,    g_G);

    reset_winner_kernel<<<1024, 1024>>>();
    edge_kernel<<<NEDGE / 256, 256>>>(ea, We, be, eidx);

    gemm_qkv<<<dim3(12, 32), 256>>>(h, Wq, bq, Wk, bk, Wv, bv);

    attn_mma<<<dim3(N_NODES / 64, NHEAD, KSPLIT), 128>>>(pQb, pKb, pVb);
    combine_kernel<<<(N_NODES * DMODEL / 4) / 256, 256>>>();

    gemm64<<<dim3(4, 32), 256>>>(pAttn, Wo, bo, h, pY, DMODEL, DMODEL, 0);

    ln_kernel<<<N_NODES / 8, 256>>>(pY, ln1g, ln1b, flng, flnb, pH1, pX2);

    gemm64<<<dim3(8, 32), 256>>>(pX2, W1, b1, nullptr, pG, HID, DMODEL, 1);
    gemm64<<<dim3(4, 32), 256>>>(pG, W2, b2, pH1, out, DMODEL, HID, 0);
}